// round 8
// baseline (speedup 1.0000x reference)
#include <cuda_runtime.h>
#include <cuda_bf16.h>

// Seq2SeqLoss: label-smoothed weighted cross-entropy, mean over masked rows.
// Harness canonical dtypes:
//   [0] outputs  f32 [B*S*C] = 131072000
//   [1] gold     i32 [B*S]   = 4096
//   [2] mask     i32 [B*S]   = 4096
//   [3] weight   f32 [C]     = 32000
// output: f32 scalar
//
// Sum factorization: with lse_r = log(sum_c exp(x_rc)), dd_r = sum_c w_c x_rc,
//   sum_r loss_r = uniform*(sumW*Σlse − Σdd) + (conf−uniform)*Σ w_g (lse − x_g)
// so sumW is only needed once, by the last-finishing CTA.

#define SMOOTHING 0.1f
#define EPSILON   1e-8f
#define SUMW_CTAS 8

__device__ float        g_sumw;       // all reset by the finalizing CTA
__device__ float        g_lse_acc;
__device__ float        g_dot_acc;
__device__ float        g_gold_acc;
__device__ float        g_mask_acc;
__device__ unsigned int g_done;       // completion counter (last-CTA-done)

// All-FMA exp (no MUFU): exp(x) = 2^(x*log2e), magic-number round,
// degree-5 poly for 2^f on [-0.5,0.5] (rel err ~2.4e-6), exponent splice.
__device__ __forceinline__ float fexp(float x) {
    float t = x * 1.4426950408889634f;
    t = fminf(fmaxf(t, -126.0f), 126.0f);
    float r = t + 12582912.0f;
    int   eb = __float_as_int(r) << 23;
    float nf = r - 12582912.0f;
    float f  = t - nf;
    float p  = 1.3333558146428443e-3f;
    p = fmaf(p, f, 9.6181291076284772e-3f);
    p = fmaf(p, f, 5.5504108664821580e-2f);
    p = fmaf(p, f, 2.4022650695910072e-1f);
    p = fmaf(p, f, 6.9314718055994531e-1f);
    p = fmaf(p, f, 1.0f);
    return __int_as_float(__float_as_int(p) + eb);
}

__device__ __forceinline__ float warp_sum(float v) {
    #pragma unroll
    for (int o = 16; o > 0; o >>= 1) v += __shfl_xor_sync(0xffffffffu, v, o);
    return v;
}

// Thread 0 of each CTA calls this after its accumulator REDs are issued.
// The last CTA to arrive computes the final output and resets state.
__device__ __forceinline__ void arrive_and_maybe_finalize(
    float* __restrict__ out, int C, unsigned int total_ctas)
{
    __threadfence();  // order this CTA's REDs before the counter bump
    unsigned int prev = atomicAdd(&g_done, 1u);
    if (prev == total_ctas - 1u) {
        __threadfence();  // ensure all other CTAs' REDs are visible
        const float uniform = SMOOTHING / (float)(C - 1);
        const float conf    = 1.0f - SMOOTHING;
        const float cmu     = conf - uniform;

        float loss_sum = uniform * fmaf(g_sumw, g_lse_acc, -g_dot_acc)
                       + cmu * g_gold_acc;
        out[0] = loss_sum / (g_mask_acc + EPSILON);

        // reset for next graph replay (deterministic)
        g_sumw = 0.0f; g_lse_acc = 0.0f; g_dot_acc = 0.0f;
        g_gold_acc = 0.0f; g_mask_acc = 0.0f;
        __threadfence();
        g_done = 0u;
    }
}

// Grid = N + SUMW_CTAS.
// CTAs [0, N):   one row each — proven streaming loop, post-loop gold gather,
//                4 scalar REDs, then last-CTA-done finalize.
// CTAs [N, N+8): sum a slice of weight into g_sumw (in the shadow).
__global__ __launch_bounds__(256) void row_loss_kernel(
    const float* __restrict__ logits,
    const int*   __restrict__ gold,
    const int*   __restrict__ mask,
    const float* __restrict__ weight,
    float* __restrict__ out,
    int C4, int C, int N)
{
    const int bid = blockIdx.x;
    const float4* wp = reinterpret_cast<const float4*>(weight);
    const unsigned int total_ctas = (unsigned int)(N + SUMW_CTAS);

    if (bid >= N) {
        // ---- sumW slice CTA ----
        const int slice = bid - N;
        const int per   = (C4 + SUMW_CTAS - 1) / SUMW_CTAS;
        const int lo    = slice * per;
        const int hi    = min(lo + per, C4);
        float w = 0.0f;
        for (int i = lo + threadIdx.x; i < hi; i += 256) {
            float4 v = __ldg(wp + i);
            w += v.x + v.y + v.z + v.w;
        }
        __shared__ float shw[8];
        w = warp_sum(w);
        if ((threadIdx.x & 31) == 0) shw[threadIdx.x >> 5] = w;
        __syncthreads();
        if (threadIdx.x == 0) {
            float ww = 0.0f;
            #pragma unroll
            for (int k = 0; k < 8; k++) ww += shw[k];
            atomicAdd(&g_sumw, ww);
            arrive_and_maybe_finalize(out, C, total_ctas);
        }
        return;
    }

    // ---- row CTA: streaming loop identical to the proven version ----
    const int row = bid;
    const float4* lp = reinterpret_cast<const float4*>(logits) + (size_t)row * C4;

    float s = 0.0f, d = 0.0f;
    #pragma unroll 4
    for (int i = threadIdx.x; i < C4; i += 256) {
        float4 x = __ldcs(lp + i);
        float4 w = __ldg(wp + i);
        d = fmaf(x.x, w.x, d);
        d = fmaf(x.y, w.y, d);
        d = fmaf(x.z, w.z, d);
        d = fmaf(x.w, w.w, d);
        s += fexp(x.x);
        s += fexp(x.y);
        s += fexp(x.z);
        s += fexp(x.w);
    }

    __shared__ float sh_s[8], sh_d[8];
    s = warp_sum(s);
    d = warp_sum(d);
    const int wid = threadIdx.x >> 5;
    const int lid = threadIdx.x & 31;
    if (lid == 0) { sh_s[wid] = s; sh_d[wid] = d; }
    __syncthreads();

    if (threadIdx.x == 0) {
        if (mask[row] != 0) {
            float ss = 0.0f, dd = 0.0f;
            #pragma unroll
            for (int k = 0; k < 8; k++) { ss += sh_s[k]; dd += sh_d[k]; }

            int   g   = gold[row];
            float xg  = __ldg(logits + (size_t)row * C + (size_t)g);
            float wg  = __ldg(weight + g);
            float lse = logf(ss);

            atomicAdd(&g_lse_acc,  lse);
            atomicAdd(&g_dot_acc,  dd);
            atomicAdd(&g_gold_acc, wg * (lse - xg));
            atomicAdd(&g_mask_acc, 1.0f);
        }
        arrive_and_maybe_finalize(out, C, total_ctas);
    }
}

extern "C" void kernel_launch(void* const* d_in, const int* in_sizes, int n_in,
                              void* d_out, int out_size)
{
    const float* logits = (const float*)d_in[0];
    const int*   gold   = (const int*)d_in[1];
    const int*   mask   = (const int*)d_in[2];
    const float* weight = (const float*)d_in[3];
    float*       out    = (float*)d_out;

    const int N = in_sizes[1];     // B*S rows
    const int C = in_sizes[3];     // classes
    const int C4 = C / 4;

    row_loss_kernel<<<N + SUMW_CTAS, 256>>>(logits, gold, mask, weight, out, C4, C, N);
}